// round 9
// baseline (speedup 1.0000x reference)
#include <cuda_runtime.h>
#include <cstddef>

// Inputs (metadata order):
//  0: transformation  float32  (4,4)
//  1: src_points      float32  (N,4)
//  2: tar_points      float32  (N,4)
//  3: covs_src        float32  (N,4,4)
//  4: covs_tar        float32  (N,4,4)
//  5: nearest_indices int32    (N,)
// Output: scalar float = 0.5 * mean(maha)
//
// Two-kernel binning scheme:
//  1) scatter: bin (j, i) pairs into 64 target-range buckets (smem-aggregated
//     reservations -> ~1 global atomic per block per bucket).
//  2) main: process pairs bucket-major. Concurrent blocks span ~6 buckets ->
//     the active covs_tar/tar gather region (~16MB) stays L2-resident, so
//     duplicate-index and shared-sector re-references hit L2 instead of DRAM.
//     All threads active (unlike the R6/R7 filtered passes) -> full MLP.
// State (cursors, accumulator) self-resets via last-block trick each replay.

#define NB    64
#define CAP   49152            // slots per bucket; 192*256, ~1.57x mean load
#define NMAX  2100000

__device__ int2  g_pairs[NB * CAP];    // ~25MB
__device__ int2  g_overflow[NMAX];     // ~17MB safety spill (normally unused)
__device__ int   g_cursor[NB];
__device__ int   g_ovf_cursor;
__device__ float g_accum;
__device__ unsigned int g_arrive;

__global__ __launch_bounds__(1024) void gicp_scatter(
    const int* __restrict__ idx, int n, int shift)
{
    __shared__ int s_cnt[NB];
    __shared__ int s_base[NB];
    __shared__ int s_ovfbase[NB];

    const int tid = threadIdx.x;
    const int i   = blockIdx.x * 1024 + tid;
    const bool valid = (i < n);

    if (tid < NB) s_cnt[tid] = 0;
    __syncthreads();

    int j = 0, b = 0, r = 0;
    if (valid) {
        j = __ldg(idx + i);
        b = j >> shift;                  // < NB by construction of shift
        r = atomicAdd(&s_cnt[b], 1);
    }
    __syncthreads();

    if (tid < NB) {
        const int cnt = s_cnt[tid];
        if (cnt > 0) {
            const int base = atomicAdd(&g_cursor[tid], cnt);
            s_base[tid] = base;
            const int endp = base + cnt;
            if (endp > CAP) {
                const int fit_end = base > CAP ? base : CAP;
                s_ovfbase[tid] = atomicAdd(&g_ovf_cursor, endp - fit_end);
            }
        }
    }
    __syncthreads();

    if (valid) {
        const int base = s_base[b];
        const int pos  = base + r;
        if (pos < CAP) {
            g_pairs[b * CAP + pos] = make_int2(j, i);
        } else {
            const int fit_end = base > CAP ? base : CAP;
            g_overflow[s_ovfbase[b] + (pos - fit_end)] = make_int2(j, i);
        }
    }
}

__device__ __forceinline__ float gicp_point(
    const float* __restrict__ t,
    const float4* __restrict__ src,
    const float4* __restrict__ tar,
    const float4* __restrict__ covs_src,
    const float4* __restrict__ covs_tar,
    int i, int j, float scale)
{
    const float4 s  = __ldg(src + (size_t)i);
    const float4 c0 = __ldg(covs_src + 4 * (size_t)i + 0);
    const float4 c1 = __ldg(covs_src + 4 * (size_t)i + 1);
    const float4 c2 = __ldg(covs_src + 4 * (size_t)i + 2);
    const float4 tp = __ldg(tar + (size_t)j);
    const float4 d0 = __ldg(covs_tar + 4 * (size_t)j + 0);
    const float4 d1 = __ldg(covs_tar + 4 * (size_t)j + 1);
    const float4 d2 = __ldg(covs_tar + 4 * (size_t)j + 2);

    const float tsx = s.x * t[0] + s.y * t[4] + s.z * t[8]  + s.w * t[12];
    const float tsy = s.x * t[1] + s.y * t[5] + s.z * t[9]  + s.w * t[13];
    const float tsz = s.x * t[2] + s.y * t[6] + s.z * t[10] + s.w * t[14];

    const float rx = tp.x - tsx;
    const float ry = tp.y - tsy;
    const float rz = tp.z - tsz;

    const float C00 = c0.x, C01 = c0.y, C02 = c0.z;
    const float C10 = c1.x, C11 = c1.y, C12 = c1.z;
    const float C20 = c2.x, C21 = c2.y, C22 = c2.z;

    float B[3][3];
    #pragma unroll
    for (int a = 0; a < 3; ++a) {
        const float r0 = t[4 * a + 0], r1 = t[4 * a + 1], r2 = t[4 * a + 2];
        B[a][0] = r0 * C00 + r1 * C10 + r2 * C20;
        B[a][1] = r0 * C01 + r1 * C11 + r2 * C21;
        B[a][2] = r0 * C02 + r1 * C12 + r2 * C22;
    }

    const float ma = B[0][0] * t[0] + B[0][1] * t[1] + B[0][2] * t[2]  + d0.x;
    const float mb = B[0][0] * t[4] + B[0][1] * t[5] + B[0][2] * t[6]  + d0.y;
    const float mc = B[0][0] * t[8] + B[0][1] * t[9] + B[0][2] * t[10] + d0.z;
    const float md = B[1][0] * t[4] + B[1][1] * t[5] + B[1][2] * t[6]  + d1.y;
    const float me = B[1][0] * t[8] + B[1][1] * t[9] + B[1][2] * t[10] + d1.z;
    const float mf = B[2][0] * t[8] + B[2][1] * t[9] + B[2][2] * t[10] + d2.z;

    const float adj00 = md * mf - me * me;
    const float adj01 = mc * me - mb * mf;
    const float adj02 = mb * me - mc * md;
    const float det   = ma * adj00 + mb * adj01 + mc * adj02;
    const float adj11 = ma * mf - mc * mc;
    const float adj12 = mb * mc - ma * me;
    const float adj22 = ma * md - mb * mb;

    const float q =
        rx * (rx * adj00 + ry * adj01 + rz * adj02) +
        ry * (rx * adj01 + ry * adj11 + rz * adj12) +
        rz * (rx * adj02 + ry * adj12 + rz * adj22);

    return (q / det) * scale;
}

__global__ __launch_bounds__(256) void gicp_main(
    const float*  __restrict__ T,
    const float4* __restrict__ src,
    const float4* __restrict__ tar,
    const float4* __restrict__ covs_src,
    const float4* __restrict__ covs_tar,
    float* __restrict__ out, float scale)
{
    const int slot = blockIdx.x * 256 + threadIdx.x;
    const int b    = slot / CAP;
    const int s    = slot % CAP;

    float t[16];
    #pragma unroll
    for (int k = 0; k < 16; ++k) t[k] = __ldg(T + k);

    float acc = 0.0f;

    // bucket-major slot
    {
        const int cur = g_cursor[b];
        const int cnt = cur < CAP ? cur : CAP;
        if (s < cnt) {
            const int2 pr = g_pairs[b * CAP + s];
            acc += gicp_point(t, src, tar, covs_src, covs_tar, pr.y, pr.x, scale);
        }
    }

    // overflow spill (normally empty)
    {
        const int ovf = g_ovf_cursor;
        if (slot < ovf) {
            const int2 pr = g_overflow[slot];
            acc += gicp_point(t, src, tar, covs_src, covs_tar, pr.y, pr.x, scale);
        }
    }

    // Warp reduce
    #pragma unroll
    for (int o = 16; o > 0; o >>= 1)
        acc += __shfl_down_sync(0xffffffffu, acc, o);

    __shared__ float ws[8];
    if ((threadIdx.x & 31) == 0) ws[threadIdx.x >> 5] = acc;
    __syncthreads();

    if (threadIdx.x < 8) {
        float v = ws[threadIdx.x];
        #pragma unroll
        for (int o = 4; o > 0; o >>= 1)
            v += __shfl_down_sync(0xffu, v, o);
        if (threadIdx.x == 0) {
            atomicAdd(&g_accum, v);
            __threadfence();
            const unsigned int prev = atomicInc(&g_arrive, 0xffffffffu);
            if (prev == gridDim.x - 1) {
                // Last block: publish result and reset all state for the
                // next graph replay.
                out[0] = atomicExch(&g_accum, 0.0f);
                #pragma unroll
                for (int k = 0; k < NB; ++k) g_cursor[k] = 0;
                g_ovf_cursor = 0;
                g_arrive = 0;
            }
        }
    }
}

extern "C" void kernel_launch(void* const* d_in, const int* in_sizes, int n_in,
                              void* d_out, int out_size)
{
    const float*  T        = (const float*) d_in[0];
    const float4* src      = (const float4*)d_in[1];
    const float4* tar      = (const float4*)d_in[2];
    const float4* covs_src = (const float4*)d_in[3];
    const float4* covs_tar = (const float4*)d_in[4];
    const int*    idx      = (const int*)   d_in[5];
    float* out = (float*)d_out;

    const int n     = in_sizes[5];
    const int n_tar = in_sizes[2] / 4;
    const float scale = 0.5f / (float)n;

    // shift: smallest s with ((n_tar-1) >> s) < NB
    int shift = 0;
    while (((n_tar - 1) >> shift) >= NB) ++shift;
    const int nb_used = ((n_tar - 1) >> shift) + 1;

    const int scat_grid = (n + 1023) / 1024;
    gicp_scatter<<<scat_grid, 1024>>>(idx, n, shift);

    const int main_grid = (nb_used * CAP) / 256;   // CAP divisible by 256
    gicp_main<<<main_grid, 256>>>(T, src, tar, covs_src, covs_tar, out, scale);
}

// round 10
// speedup vs baseline: 1.4153x; 1.4153x over previous
#include <cuda_runtime.h>
#include <cstddef>

// Inputs (metadata order):
//  0: transformation  float32  (4,4)
//  1: src_points      float32  (N,4)
//  2: tar_points      float32  (N,4)
//  3: covs_src        float32  (N,4,4)
//  4: covs_tar        float32  (N,4,4)
//  5: nearest_indices int32    (N,)
// Output: scalar float = 0.5 * mean(maha)
//
// R1 body, 2 points per thread (split-half indexing keeps both streams
// coalesced). All 16 wide loads issued before any compute -> 2x outstanding
// LDGs per warp to cover the ~600-cycle random-gather latency and push
// DRAM% above the 80% plateau. Single launch; device-global accumulator
// with last-block publish/reset (graph-replay safe).

__device__ float        g_accum;
__device__ unsigned int g_count;

struct P {
    float4 s, c0, c1, c2, tp, d0, d1, d2;
};

__device__ __forceinline__ float gicp_eval(const float* __restrict__ t,
                                           const P& p)
{
    const float4 s = p.s, tp = p.tp;
    const float4 c0 = p.c0, c1 = p.c1, c2 = p.c2;
    const float4 d0 = p.d0, d1 = p.d1, d2 = p.d2;

    const float tsx = s.x * t[0] + s.y * t[4] + s.z * t[8]  + s.w * t[12];
    const float tsy = s.x * t[1] + s.y * t[5] + s.z * t[9]  + s.w * t[13];
    const float tsz = s.x * t[2] + s.y * t[6] + s.z * t[10] + s.w * t[14];

    const float rx = tp.x - tsx;
    const float ry = tp.y - tsy;
    const float rz = tp.z - tsz;

    const float C00 = c0.x, C01 = c0.y, C02 = c0.z;
    const float C10 = c1.x, C11 = c1.y, C12 = c1.z;
    const float C20 = c2.x, C21 = c2.y, C22 = c2.z;

    float B[3][3];
    #pragma unroll
    for (int a = 0; a < 3; ++a) {
        const float r0 = t[4 * a + 0], r1 = t[4 * a + 1], r2 = t[4 * a + 2];
        B[a][0] = r0 * C00 + r1 * C10 + r2 * C20;
        B[a][1] = r0 * C01 + r1 * C11 + r2 * C21;
        B[a][2] = r0 * C02 + r1 * C12 + r2 * C22;
    }

    const float ma = B[0][0] * t[0] + B[0][1] * t[1] + B[0][2] * t[2]  + d0.x;
    const float mb = B[0][0] * t[4] + B[0][1] * t[5] + B[0][2] * t[6]  + d0.y;
    const float mc = B[0][0] * t[8] + B[0][1] * t[9] + B[0][2] * t[10] + d0.z;
    const float md = B[1][0] * t[4] + B[1][1] * t[5] + B[1][2] * t[6]  + d1.y;
    const float me = B[1][0] * t[8] + B[1][1] * t[9] + B[1][2] * t[10] + d1.z;
    const float mf = B[2][0] * t[8] + B[2][1] * t[9] + B[2][2] * t[10] + d2.z;

    const float adj00 = md * mf - me * me;
    const float adj01 = mc * me - mb * mf;
    const float adj02 = mb * me - mc * md;
    const float det   = ma * adj00 + mb * adj01 + mc * adj02;
    const float adj11 = ma * mf - mc * mc;
    const float adj12 = mb * mc - ma * me;
    const float adj22 = ma * md - mb * mb;

    const float q =
        rx * (rx * adj00 + ry * adj01 + rz * adj02) +
        ry * (rx * adj01 + ry * adj11 + rz * adj12) +
        rz * (rx * adj02 + ry * adj12 + rz * adj22);

    return q / det;
}

__device__ __forceinline__ void gicp_load(
    P& p,
    const float4* __restrict__ src,
    const float4* __restrict__ tar,
    const float4* __restrict__ covs_src,
    const float4* __restrict__ covs_tar,
    int i, int j)
{
    p.s  = __ldg(src + (size_t)i);
    p.c0 = __ldg(covs_src + 4 * (size_t)i + 0);
    p.c1 = __ldg(covs_src + 4 * (size_t)i + 1);
    p.c2 = __ldg(covs_src + 4 * (size_t)i + 2);
    p.tp = __ldg(tar + (size_t)j);
    p.d0 = __ldg(covs_tar + 4 * (size_t)j + 0);
    p.d1 = __ldg(covs_tar + 4 * (size_t)j + 1);
    p.d2 = __ldg(covs_tar + 4 * (size_t)j + 2);
}

__global__ __launch_bounds__(256) void gicp_kernel(
    const float*  __restrict__ T,
    const float4* __restrict__ src,
    const float4* __restrict__ tar,
    const float4* __restrict__ covs_src,
    const float4* __restrict__ covs_tar,
    const int*    __restrict__ idx,
    float*        __restrict__ out,
    int n, int half, float scale)
{
    // Thread handles points i0 (first half) and i1 = i0 + half (second half):
    // both index streams stay fully coalesced across the warp.
    const int i0 = blockIdx.x * blockDim.x + threadIdx.x;
    const int i1 = i0 + half;

    float t[16];
    #pragma unroll
    for (int k = 0; k < 16; ++k) t[k] = __ldg(T + k);

    float acc = 0.0f;

    const bool v0 = (i0 < half);        // i0 < half <= n
    const bool v1 = (i1 < n);

    int j0 = 0, j1 = 0;
    if (v0) j0 = __ldg(idx + i0);
    if (v1) j1 = __ldg(idx + i1);

    P p0, p1;
    if (v0) gicp_load(p0, src, tar, covs_src, covs_tar, i0, j0);
    if (v1) gicp_load(p1, src, tar, covs_src, covs_tar, i1, j1);

    if (v0) acc += gicp_eval(t, p0);
    if (v1) acc += gicp_eval(t, p1);
    acc *= scale;

    // Warp reduce
    #pragma unroll
    for (int o = 16; o > 0; o >>= 1)
        acc += __shfl_down_sync(0xffffffffu, acc, o);

    __shared__ float ws[8];
    if ((threadIdx.x & 31) == 0) ws[threadIdx.x >> 5] = acc;
    __syncthreads();

    if (threadIdx.x < 8) {
        float v = ws[threadIdx.x];
        #pragma unroll
        for (int o = 4; o > 0; o >>= 1)
            v += __shfl_down_sync(0xffu, v, o);
        if (threadIdx.x == 0) {
            atomicAdd(&g_accum, v);
            __threadfence();
            const unsigned int prev = atomicInc(&g_count, 0xffffffffu);
            if (prev == gridDim.x - 1) {
                out[0] = atomicExch(&g_accum, 0.0f);
                g_count = 0;
            }
        }
    }
}

extern "C" void kernel_launch(void* const* d_in, const int* in_sizes, int n_in,
                              void* d_out, int out_size)
{
    const float*  T        = (const float*) d_in[0];
    const float4* src      = (const float4*)d_in[1];
    const float4* tar      = (const float4*)d_in[2];
    const float4* covs_src = (const float4*)d_in[3];
    const float4* covs_tar = (const float4*)d_in[4];
    const int*    idx      = (const int*)   d_in[5];
    float* out = (float*)d_out;

    const int n = in_sizes[5];
    const int half = (n + 1) / 2;
    const float scale = 0.5f / (float)n;

    const int tpb = 256;
    const int grid = (half + tpb - 1) / tpb;
    gicp_kernel<<<grid, tpb>>>(T, src, tar, covs_src, covs_tar, idx, out,
                               n, half, scale);
}

// round 11
// speedup vs baseline: 1.4340x; 1.0132x over previous
#include <cuda_runtime.h>
#include <cstddef>

// Inputs (metadata order):
//  0: transformation  float32  (4,4)
//  1: src_points      float32  (N,4)
//  2: tar_points      float32  (N,4)
//  3: covs_src        float32  (N,4,4)
//  4: covs_tar        float32  (N,4,4)
//  5: nearest_indices int32    (N,)
// Output: scalar float = 0.5 * mean(maha)
//
// Final kernel: HBM-bound gather+reduce at the measured roofline
// (~80% DRAM, 6.35TB/s over ~449MB effective traffic = ~70us).
// Campaign notes: L2 eviction hints (R4/R5), target partitioning (R6/R7),
// index binning (R9), launch fusion (R8), and 2pt/thread MLP (R10) all
// measured neutral or worse; this R1 configuration is the optimum.
// Key algorithmic choice: res^T adj(M) res / det(M) instead of forming the
// 3x3 inverse (M is SPD with min eigenvalue >= 0.1 -> well conditioned;
// rel_err ~3e-6).

__global__ void gicp_zero_out(float* out) {
    if (blockIdx.x == 0 && threadIdx.x == 0) out[0] = 0.0f;
}

__global__ __launch_bounds__(256) void gicp_kernel(
    const float*  __restrict__ T,         // 16 floats
    const float4* __restrict__ src,       // N rows (x,y,z,1)
    const float4* __restrict__ tar,       // N rows
    const float4* __restrict__ covs_src,  // N * 4 rows
    const float4* __restrict__ covs_tar,  // N * 4 rows
    const int*    __restrict__ idx,       // N
    float*        __restrict__ out,
    int n, float scale)
{
    const int i = blockIdx.x * blockDim.x + threadIdx.x;
    float acc = 0.0f;

    if (i < n) {
        // Broadcast load of the 4x4 transformation (L1 hit after warmup).
        float t[16];
        #pragma unroll
        for (int k = 0; k < 16; ++k) t[k] = __ldg(T + k);

        const int j = __ldg(idx + i);

        // Issue all memory traffic up front for MLP.
        const float4 s  = __ldg(src + (size_t)i);
        const float4 c0 = __ldg(covs_src + 4 * (size_t)i + 0);
        const float4 c1 = __ldg(covs_src + 4 * (size_t)i + 1);
        const float4 c2 = __ldg(covs_src + 4 * (size_t)i + 2);
        const float4 tp = __ldg(tar + (size_t)j);
        const float4 d0 = __ldg(covs_tar + 4 * (size_t)j + 0);
        const float4 d1 = __ldg(covs_tar + 4 * (size_t)j + 1);
        const float4 d2 = __ldg(covs_tar + 4 * (size_t)j + 2);

        // transformed_src = src_row_vector @ T  (take xyz)
        const float tsx = s.x * t[0] + s.y * t[4] + s.z * t[8]  + s.w * t[12];
        const float tsy = s.x * t[1] + s.y * t[5] + s.z * t[9]  + s.w * t[13];
        const float tsz = s.x * t[2] + s.y * t[6] + s.z * t[10] + s.w * t[14];

        const float rx = tp.x - tsx;
        const float ry = tp.y - tsy;
        const float rz = tp.z - tsz;

        // R = T[:3,:3] (row-major: R[a][k] = t[4a+k]).
        // B = R * C3 ;  tcov3 = B * R^T ; M = Ctar3 + tcov3 (symmetric).
        const float C00 = c0.x, C01 = c0.y, C02 = c0.z;
        const float C10 = c1.x, C11 = c1.y, C12 = c1.z;
        const float C20 = c2.x, C21 = c2.y, C22 = c2.z;

        float B[3][3];
        #pragma unroll
        for (int a = 0; a < 3; ++a) {
            const float r0 = t[4 * a + 0], r1 = t[4 * a + 1], r2 = t[4 * a + 2];
            B[a][0] = r0 * C00 + r1 * C10 + r2 * C20;
            B[a][1] = r0 * C01 + r1 * C11 + r2 * C21;
            B[a][2] = r0 * C02 + r1 * C12 + r2 * C22;
        }

        // Symmetric M = [a b c; b d e; c e f]
        const float ma = B[0][0] * t[0] + B[0][1] * t[1] + B[0][2] * t[2]  + d0.x;
        const float mb = B[0][0] * t[4] + B[0][1] * t[5] + B[0][2] * t[6]  + d0.y;
        const float mc = B[0][0] * t[8] + B[0][1] * t[9] + B[0][2] * t[10] + d0.z;
        const float md = B[1][0] * t[4] + B[1][1] * t[5] + B[1][2] * t[6]  + d1.y;
        const float me = B[1][0] * t[8] + B[1][1] * t[9] + B[1][2] * t[10] + d1.z;
        const float mf = B[2][0] * t[8] + B[2][1] * t[9] + B[2][2] * t[10] + d2.z;

        // maha = res^T adj(M) res / det(M)
        const float adj00 = md * mf - me * me;
        const float adj01 = mc * me - mb * mf;
        const float adj02 = mb * me - mc * md;
        const float det   = ma * adj00 + mb * adj01 + mc * adj02;
        const float adj11 = ma * mf - mc * mc;
        const float adj12 = mb * mc - ma * me;
        const float adj22 = ma * md - mb * mb;

        const float q =
            rx * (rx * adj00 + ry * adj01 + rz * adj02) +
            ry * (rx * adj01 + ry * adj11 + rz * adj12) +
            rz * (rx * adj02 + ry * adj12 + rz * adj22);

        acc = (q / det) * scale;   // scale = 0.5 / N folded in
    }

    // Warp reduce
    #pragma unroll
    for (int o = 16; o > 0; o >>= 1)
        acc += __shfl_down_sync(0xffffffffu, acc, o);

    __shared__ float ws[8];
    if ((threadIdx.x & 31) == 0) ws[threadIdx.x >> 5] = acc;
    __syncthreads();

    if (threadIdx.x < 8) {
        float v = ws[threadIdx.x];
        #pragma unroll
        for (int o = 4; o > 0; o >>= 1)
            v += __shfl_down_sync(0xffu, v, o);
        if (threadIdx.x == 0) atomicAdd(out, v);
    }
}

extern "C" void kernel_launch(void* const* d_in, const int* in_sizes, int n_in,
                              void* d_out, int out_size)
{
    const float*  T        = (const float*) d_in[0];
    const float4* src      = (const float4*)d_in[1];
    const float4* tar      = (const float4*)d_in[2];
    const float4* covs_src = (const float4*)d_in[3];
    const float4* covs_tar = (const float4*)d_in[4];
    const int*    idx      = (const int*)   d_in[5];
    float* out = (float*)d_out;

    const int n = in_sizes[5];          // N points
    const float scale = 0.5f / (float)n;

    gicp_zero_out<<<1, 32>>>(out);

    const int tpb = 256;
    const int grid = (n + tpb - 1) / tpb;
    gicp_kernel<<<grid, tpb>>>(T, src, tar, covs_src, covs_tar, idx, out, n, scale);
}